// round 6
// baseline (speedup 1.0000x reference)
#include <cuda_runtime.h>
#include <cstdint>
#include <cstddef>

#define HID 512
#define TT  1024
#define NB  128
#define RTOT (NB*TT)

// ping-pong activation buffers (xp in / ys out, in place), 256 MB each
__device__ float g_bufA[(size_t)RTOT * HID];
__device__ float g_bufB[(size_t)RTOT * HID];

// ---------------- helpers ----------------
__device__ __forceinline__ uint32_t smem_u32(const void* p) {
    return (uint32_t)__cvta_generic_to_shared(p);
}
__device__ __forceinline__ uint32_t mapa_u32(uint32_t addr, uint32_t rank) {
    uint32_t r;
    asm("mapa.shared::cluster.u32 %0, %1, %2;" : "=r"(r) : "r"(addr), "r"(rank));
    return r;
}
__device__ __forceinline__ void st_cluster_f32(uint32_t addr, float v) {
    asm volatile("st.shared::cluster.f32 [%0], %1;" :: "r"(addr), "f"(v) : "memory");
}
__device__ __forceinline__ void cluster_sync_all() {
    asm volatile("barrier.cluster.arrive.aligned;" ::: "memory");
    asm volatile("barrier.cluster.wait.aligned;" ::: "memory");
}
__device__ __forceinline__ uint32_t ctarank() {
    uint32_t r; asm("mov.u32 %0, %%cluster_ctarank;" : "=r"(r)); return r;
}
// accurate tanh, immune to --use_fast_math's tanh.approx (err 2^-11 too big here)
__device__ __forceinline__ float my_tanh(float x) {
    float e = __expf(2.0f * x);
    return 1.0f - 2.0f / (e + 1.0f);
}

// ---------------- xp0: (B*T,24) @ W_ih0^T -> (B*T,512) + bias ----------------
__global__ __launch_bounds__(256) void xp0_kernel(
    const float* __restrict__ x, const float* __restrict__ Wih,
    const float* __restrict__ bi, const float* __restrict__ bh,
    float* __restrict__ out)
{
    __shared__ float xs[32 * 24];
    int tid = threadIdx.x;
    int r0 = blockIdx.x * 32;
    int h0 = tid * 2;

    float w0[24], w1[24];
    const float4* wp0 = (const float4*)(Wih + (size_t)h0 * 24);
    #pragma unroll
    for (int i = 0; i < 6; i++) {
        float4 v = wp0[i];
        w0[4*i] = v.x; w0[4*i+1] = v.y; w0[4*i+2] = v.z; w0[4*i+3] = v.w;
    }
    const float4* wp1 = (const float4*)(Wih + (size_t)(h0 + 1) * 24);
    #pragma unroll
    for (int i = 0; i < 6; i++) {
        float4 v = wp1[i];
        w1[4*i] = v.x; w1[4*i+1] = v.y; w1[4*i+2] = v.z; w1[4*i+3] = v.w;
    }
    float bias0 = bi[h0] + bh[h0];
    float bias1 = bi[h0 + 1] + bh[h0 + 1];

    for (int i = tid; i < 32 * 24; i += 256) xs[i] = x[(size_t)r0 * 24 + i];
    __syncthreads();

    #pragma unroll 4
    for (int rr = 0; rr < 32; rr++) {
        float a0 = bias0, a1 = bias1;
        #pragma unroll
        for (int f = 0; f < 24; f++) {
            float xv = xs[rr * 24 + f];
            a0 = fmaf(w0[f], xv, a0);
            a1 = fmaf(w1[f], xv, a1);
        }
        *(float2*)(out + (size_t)(r0 + rr) * HID + h0) = make_float2(a0, a1);
    }
}

// ---------------- SGEMM: C[r][j] = bias[j] + sum_k A[r][k]*W[j][k] ----------------
#define GBM 128
#define GBN 128
#define GBK 16
__global__ __launch_bounds__(256, 2) void sgemm_kernel(
    const float* __restrict__ A, const float* __restrict__ W,
    const float* __restrict__ bi, const float* __restrict__ bh,
    float* __restrict__ C)
{
    __shared__ __align__(16) float As[2][GBK][GBM + 4];
    __shared__ __align__(16) float Ws[2][GBK][GBN + 4];

    int tid = threadIdx.x;
    int r0 = blockIdx.y * GBM;
    int j0 = blockIdx.x * GBN;
    int tx = tid & 15, ty = tid >> 4;

    float4 ra[2], rw[2];
    float acc[8][8];
    #pragma unroll
    for (int i = 0; i < 8; i++)
        #pragma unroll
        for (int j = 0; j < 8; j++) acc[i][j] = 0.0f;

    #pragma unroll
    for (int l = 0; l < 2; l++) {
        int idx = tid + l * 256;
        int r = idx >> 2, kq = idx & 3;
        ra[l] = *(const float4*)(A + (size_t)(r0 + r) * HID + kq * 4);
        rw[l] = *(const float4*)(W + (size_t)(j0 + r) * HID + kq * 4);
    }
    #pragma unroll
    for (int l = 0; l < 2; l++) {
        int idx = tid + l * 256;
        int r = idx >> 2, kq = idx & 3;
        As[0][kq*4+0][r] = ra[l].x; As[0][kq*4+1][r] = ra[l].y;
        As[0][kq*4+2][r] = ra[l].z; As[0][kq*4+3][r] = ra[l].w;
        Ws[0][kq*4+0][r] = rw[l].x; Ws[0][kq*4+1][r] = rw[l].y;
        Ws[0][kq*4+2][r] = rw[l].z; Ws[0][kq*4+3][r] = rw[l].w;
    }
    __syncthreads();

    for (int kt = 0; kt < HID / GBK; kt++) {
        int buf = kt & 1;
        if (kt + 1 < HID / GBK) {
            int kbase = (kt + 1) * GBK;
            #pragma unroll
            for (int l = 0; l < 2; l++) {
                int idx = tid + l * 256;
                int r = idx >> 2, kq = idx & 3;
                ra[l] = *(const float4*)(A + (size_t)(r0 + r) * HID + kbase + kq * 4);
                rw[l] = *(const float4*)(W + (size_t)(j0 + r) * HID + kbase + kq * 4);
            }
        }
        #pragma unroll
        for (int k = 0; k < GBK; k++) {
            float4 a0 = *(const float4*)&As[buf][k][ty * 8];
            float4 a1 = *(const float4*)&As[buf][k][ty * 8 + 4];
            float4 b0 = *(const float4*)&Ws[buf][k][tx * 8];
            float4 b1 = *(const float4*)&Ws[buf][k][tx * 8 + 4];
            float av[8] = {a0.x, a0.y, a0.z, a0.w, a1.x, a1.y, a1.z, a1.w};
            float bv[8] = {b0.x, b0.y, b0.z, b0.w, b1.x, b1.y, b1.z, b1.w};
            #pragma unroll
            for (int i = 0; i < 8; i++)
                #pragma unroll
                for (int j = 0; j < 8; j++)
                    acc[i][j] = fmaf(av[i], bv[j], acc[i][j]);
        }
        if (kt + 1 < HID / GBK) {
            int nb = buf ^ 1;
            #pragma unroll
            for (int l = 0; l < 2; l++) {
                int idx = tid + l * 256;
                int r = idx >> 2, kq = idx & 3;
                As[nb][kq*4+0][r] = ra[l].x; As[nb][kq*4+1][r] = ra[l].y;
                As[nb][kq*4+2][r] = ra[l].z; As[nb][kq*4+3][r] = ra[l].w;
                Ws[nb][kq*4+0][r] = rw[l].x; Ws[nb][kq*4+1][r] = rw[l].y;
                Ws[nb][kq*4+2][r] = rw[l].z; Ws[nb][kq*4+3][r] = rw[l].w;
            }
        }
        __syncthreads();
    }

    float bias[8];
    #pragma unroll
    for (int j = 0; j < 8; j++) {
        int jj = j0 + tx * 8 + j;
        bias[j] = bi[jj] + bh[jj];
    }
    #pragma unroll
    for (int i = 0; i < 8; i++) {
        int row = r0 + ty * 8 + i;
        float4 o0 = make_float4(acc[i][0] + bias[0], acc[i][1] + bias[1],
                                acc[i][2] + bias[2], acc[i][3] + bias[3]);
        float4 o1 = make_float4(acc[i][4] + bias[4], acc[i][5] + bias[5],
                                acc[i][6] + bias[6], acc[i][7] + bias[7]);
        *(float4*)(C + (size_t)row * HID + j0 + tx * 8)     = o0;
        *(float4*)(C + (size_t)row * HID + j0 + tx * 8 + 4) = o1;
    }
}

// ---------------- recurrence: 8-CTA cluster, W_hh resident in registers ----------------
// grid = 128 CTAs (16 clusters x 8), 512 threads. CTA rank c owns W_hh rows
// [64c, 64c+64). thread tid: j = tid>>3 (local out row), g = tid&7 (k-split
// lane AND batch lane), s = (g+j)&7 (k-chunk rotation -> conflict-free LDS).
// Holds W_hh[64c+j][64s .. 64s+64) in 64 registers. Per step: 8 batch x 64-k
// partial dots, 3-level shfl-bfly over g, lane g==b finalizes batch b; the
// new h value is pushed to all 8 CTAs' smem via mapa + st.shared::cluster,
// then one cluster barrier.
__global__ __launch_bounds__(512, 1) __cluster_dims__(8, 1, 1)
void rnn_kernel(float* __restrict__ xp, const float* __restrict__ Whh, int T)
{
    // h[buf][batch][chunk 0..7][64 + 4 pad] : chunk stride 272B -> the 8
    // chunks read by one warp-LDS.128 land on 8 distinct bank-quads.
    __shared__ __align__(16) float hs[2][8][8][68];
    __shared__ __align__(16) float xps[2][8][64];

    int tid = threadIdx.x;
    int j = tid >> 3, g = tid & 7;
    int s = (g + j) & 7;
    uint32_t crank = ctarank();
    int cid = blockIdx.x >> 3;      // cluster id 0..15
    int b0  = cid * 8;              // first batch row of this cluster
    int jg  = (int)crank * 64 + j;  // global h row this thread owns

    // W slice -> registers
    float w[64];
    const float4* wp = (const float4*)(Whh + (size_t)jg * HID + s * 64);
    #pragma unroll
    for (int i = 0; i < 16; i++) {
        float4 v = wp[i];
        w[4*i] = v.x; w[4*i+1] = v.y; w[4*i+2] = v.z; w[4*i+3] = v.w;
    }

    // DSMEM store targets: &hs[0][g][crank][j] in every cluster CTA
    uint32_t dst[8];
    {
        uint32_t a0 = smem_u32(&hs[0][g][crank][j]);
        #pragma unroll
        for (int r = 0; r < 8; r++) dst[r] = mapa_u32(a0, (uint32_t)r);
    }
    const uint32_t BUFOFF = (uint32_t)(8 * 8 * 68 * 4); // sizeof(hs[0])

    // h_{-1} = 0
    for (int i = tid; i < 8 * 8 * 68; i += 512) ((float*)hs[0])[i] = 0.0f;

    // stage xp[t=0]: this CTA's 64-column slice for all 8 batches (coalesced)
    int bb = tid >> 6, jj = tid & 63;
    xps[0][bb][jj] = xp[((size_t)(b0 + bb) * T + 0) * HID + crank * 64 + jj];
    __syncthreads();
    cluster_sync_all();

    for (int t = 0; t < T; t++) {
        int cur = t & 1, nxt = cur ^ 1;

        // prefetch next xp slice (hidden under the matvec)
        float xnext = 0.0f;
        if (t + 1 < T)
            xnext = xp[((size_t)(b0 + bb) * T + (t + 1)) * HID + crank * 64 + jj];

        float acc[8];
        #pragma unroll
        for (int b = 0; b < 8; b++) {
            const float4* hb = (const float4*)&hs[cur][b][s][0];
            float a0 = 0.f, a1 = 0.f, a2 = 0.f, a3 = 0.f;
            #pragma unroll
            for (int i = 0; i < 16; i++) {
                float4 hv = hb[i];
                a0 = fmaf(w[4*i],   hv.x, a0);
                a1 = fmaf(w[4*i+1], hv.y, a1);
                a2 = fmaf(w[4*i+2], hv.z, a2);
                a3 = fmaf(w[4*i+3], hv.w, a3);
            }
            acc[b] = (a0 + a1) + (a2 + a3);
        }
        // reduce the 8-way k-split (xor stays within the 8-lane g-group)
        #pragma unroll
        for (int b = 0; b < 8; b++) {
            acc[b] += __shfl_xor_sync(0xffffffffu, acc[b], 1);
            acc[b] += __shfl_xor_sync(0xffffffffu, acc[b], 2);
            acc[b] += __shfl_xor_sync(0xffffffffu, acc[b], 4);
        }
        // lane g finalizes batch b == g (static select, no dynamic reg index)
        float myacc = acc[0];
        #pragma unroll
        for (int b = 1; b < 8; b++) if (g == b) myacc = acc[b];

        float hnew = my_tanh(xps[cur][g][j] + myacc);

        // ys (in place over xp) for (batch b0+g, time t, row jg)
        xp[((size_t)(b0 + g) * T + t) * HID + jg] = hnew;

        // broadcast hnew into hs[nxt] of all 8 cluster CTAs
        uint32_t off = nxt ? BUFOFF : 0u;
        #pragma unroll
        for (int r = 0; r < 8; r++) st_cluster_f32(dst[r] + off, hnew);

        // stage next xp locally
        if (t + 1 < T) xps[nxt][bb][jj] = xnext;

        cluster_sync_all();
    }
}

// ---------------- head: last = ys2[:,T-1,:]; silu(last@W1^T+b1)@W2^T+b2 ----------------
__global__ __launch_bounds__(256) void head_kernel(
    const float* __restrict__ ys, const float* __restrict__ W1,
    const float* __restrict__ b1, const float* __restrict__ W2,
    const float* __restrict__ b2, float* __restrict__ out)
{
    __shared__ float hrow[HID];
    __shared__ float z[1024];
    int b = blockIdx.x;
    int tid = threadIdx.x, w = tid >> 5, l = tid & 31;

    const float* src = ys + ((size_t)b * TT + (TT - 1)) * HID;
    for (int i = tid; i < HID; i += 256) hrow[i] = src[i];
    __syncthreads();

    for (int m = w; m < 1024; m += 8) {
        const float4* wr = (const float4*)(W1 + (size_t)m * HID);
        float a = 0.0f;
        #pragma unroll
        for (int i = 0; i < 4; i++) {
            float4 wv = wr[l + 32 * i];
            float4 hv = *(const float4*)&hrow[4 * (l + 32 * i)];
            a = fmaf(wv.x, hv.x, a); a = fmaf(wv.y, hv.y, a);
            a = fmaf(wv.z, hv.z, a); a = fmaf(wv.w, hv.w, a);
        }
        a += __shfl_xor_sync(0xffffffffu, a, 16);
        a += __shfl_xor_sync(0xffffffffu, a, 8);
        a += __shfl_xor_sync(0xffffffffu, a, 4);
        a += __shfl_xor_sync(0xffffffffu, a, 2);
        a += __shfl_xor_sync(0xffffffffu, a, 1);
        if (l == 0) {
            float zz = a + b1[m];
            z[m] = zz / (1.0f + __expf(-zz));   // silu
        }
    }
    __syncthreads();

    // 8 outputs, one warp each
    {
        const float4* wr = (const float4*)(W2 + (size_t)w * 1024);
        float a = 0.0f;
        #pragma unroll
        for (int i = 0; i < 8; i++) {
            float4 wv = wr[l + 32 * i];
            float4 zv = *(const float4*)&z[4 * (l + 32 * i)];
            a = fmaf(wv.x, zv.x, a); a = fmaf(wv.y, zv.y, a);
            a = fmaf(wv.z, zv.z, a); a = fmaf(wv.w, zv.w, a);
        }
        a += __shfl_xor_sync(0xffffffffu, a, 16);
        a += __shfl_xor_sync(0xffffffffu, a, 8);
        a += __shfl_xor_sync(0xffffffffu, a, 4);
        a += __shfl_xor_sync(0xffffffffu, a, 2);
        a += __shfl_xor_sync(0xffffffffu, a, 1);
        if (l == 0) out[b * 8 + w] = a + b2[w];
    }
}

// ---------------- launch ----------------
extern "C" void kernel_launch(void* const* d_in, const int* in_sizes, int n_in,
                              void* d_out, int out_size) {
    const float* x     = (const float*)d_in[0];
    const float* Wih0  = (const float*)d_in[1];
    const float* Whh0  = (const float*)d_in[2];
    const float* bih0  = (const float*)d_in[3];
    const float* bhh0  = (const float*)d_in[4];
    const float* Wih1  = (const float*)d_in[5];
    const float* Whh1  = (const float*)d_in[6];
    const float* bih1  = (const float*)d_in[7];
    const float* bhh1  = (const float*)d_in[8];
    const float* Wih2  = (const float*)d_in[9];
    const float* Whh2  = (const float*)d_in[10];
    const float* bih2  = (const float*)d_in[11];
    const float* bhh2  = (const float*)d_in[12];
    const float* W1    = (const float*)d_in[13];
    const float* b1    = (const float*)d_in[14];
    const float* W2    = (const float*)d_in[15];
    const float* b2    = (const float*)d_in[16];
    float* out = (float*)d_out;

    float* bufA; cudaGetSymbolAddress((void**)&bufA, g_bufA);
    float* bufB; cudaGetSymbolAddress((void**)&bufB, g_bufB);

    // layer 0: xp0 then recurrence in place
    xp0_kernel<<<RTOT / 32, 256>>>(x, Wih0, bih0, bhh0, bufA);
    rnn_kernel<<<128, 512>>>(bufA, Whh0, TT);

    // layer 1
    sgemm_kernel<<<dim3(HID / GBN, RTOT / GBM), 256>>>(bufA, Wih1, bih1, bhh1, bufB);
    rnn_kernel<<<128, 512>>>(bufB, Whh1, TT);

    // layer 2
    sgemm_kernel<<<dim3(HID / GBN, RTOT / GBM), 256>>>(bufB, Wih2, bih2, bhh2, bufA);
    rnn_kernel<<<128, 512>>>(bufA, Whh2, TT);

    // head
    head_kernel<<<NB, 256>>>(bufA, W1, b1, W2, b2, out);
}